// round 8
// baseline (speedup 1.0000x reference)
#include <cuda_runtime.h>
#include <cstdint>

// ---------------------------------------------------------------------------
// StoX_Conv2d: 4-bit-weight / 4-plane-binarized-activation conv + per-chunk
// BatchNorm + stochastic MTJ binarization (exact JAX threefry reproduction).
// ---------------------------------------------------------------------------

#define BATCH 8
#define CIN   64
#define LDIM  1024          // 32*32
#define OUTC  128
#define ABITS 4
#define GCH   9             // NUM_CHUNKS
#define CKTOT 576           // CIN*9
#define NTOT  32            // ABITS*BATCH

// ---- static device scratch (allocation-free rule: __device__ globals) -----
__device__ __align__(16) signed char d_SP[ABITS * BATCH * CIN * 34 * 34]; // padded sign planes
__device__ __align__(16) int         d_U4[NTOT * 144 * LDIM];             // packed unfolded signs (4 ck per word)
__device__ __align__(16) int         d_Wp[144 * OUTC];                    // packed quantized weights *7
__device__ __align__(16) short       d_t7[GCH * NTOT * OUTC * LDIM];      // 7*lt exact int
__device__ float                     d_Mean[GCH * OUTC];
__device__ float                     d_Sf[GCH * OUTC];                    // sqrt(var+eps), f32

struct Keys { unsigned v[2 * GCH]; };

// ---------------- Threefry2x32 (matches jax/_src/prng.py bit-exactly) ------
__host__ __device__ __forceinline__ unsigned rotl32(unsigned x, int r) {
#if defined(__CUDA_ARCH__)
    return __funnelshift_l(x, x, r);
#else
    return (x << r) | (x >> (32 - r));
#endif
}

__host__ __device__ __forceinline__ void tf2x32(unsigned k0, unsigned k1,
                                                unsigned x0, unsigned x1,
                                                unsigned& o0, unsigned& o1) {
    unsigned k2 = k0 ^ k1 ^ 0x1BD11BDAu;
    x0 += k0; x1 += k1;
#define TF_R(r) { x0 += x1; x1 = rotl32(x1, r); x1 ^= x0; }
    TF_R(13) TF_R(15) TF_R(26) TF_R(6)
    x0 += k1; x1 += k2 + 1u;
    TF_R(17) TF_R(29) TF_R(16) TF_R(24)
    x0 += k2; x1 += k0 + 2u;
    TF_R(13) TF_R(15) TF_R(26) TF_R(6)
    x0 += k0; x1 += k1 + 3u;
    TF_R(17) TF_R(29) TF_R(16) TF_R(24)
    x0 += k1; x1 += k2 + 4u;
    TF_R(13) TF_R(15) TF_R(26) TF_R(6)
    x0 += k2; x1 += k0 + 5u;
#undef TF_R
    o0 = x0; o1 = x1;
}

// ---------------- XLA EmitTanh f32 rational (un-fused mul/add) -------------
__device__ __forceinline__ float tanh_xla(float xin) {
    float x = fminf(fmaxf(xin, -9.0f), 9.0f);
    float x2 = __fmul_rn(x, x);
    float p = -2.76076847742355e-16f;
    p = __fadd_rn(__fmul_rn(x2, p),  2.00018790482477e-13f);
    p = __fadd_rn(__fmul_rn(x2, p), -8.60467152213735e-11f);
    p = __fadd_rn(__fmul_rn(x2, p),  5.12229709037114e-08f);
    p = __fadd_rn(__fmul_rn(x2, p),  1.48572235717979e-05f);
    p = __fadd_rn(__fmul_rn(x2, p),  6.37261928875436e-04f);
    p = __fadd_rn(__fmul_rn(x2, p),  4.89352455891786e-03f);
    float num = __fmul_rn(x, p);
    float q = 1.19825839466702e-06f;
    q = __fadd_rn(__fmul_rn(x2, q), 1.18534705686654e-04f);
    q = __fadd_rn(__fmul_rn(x2, q), 2.26843463243900e-03f);
    q = __fadd_rn(__fmul_rn(x2, q), 4.89352518554385e-03f);
    float r = __fdiv_rn(num, q);
    return (fabsf(xin) < 0.0004f) ? xin : r;
}

// ---------------- kFill: pad-value fill of sign planes ---------------------
// sign planes of input value 0: a=0 -> +1, a=1..3 -> -1
__global__ void kFill() {
    int i = blockIdx.x * 256 + threadIdx.x;
    const int tot = ABITS * BATCH * CIN * 34 * 34;
    if (i < tot) {
        int a = i / (BATCH * CIN * 34 * 34);
        d_SP[i] = (a == 0) ? 1 : -1;
    }
}

// ---------------- kS1: interior sign planes (exact f32 residual steps) -----
__global__ void kS1(const float* __restrict__ inp) {
    int i = blockIdx.x * 256 + threadIdx.x;          // over 8*64*1024
    if (i >= BATCH * CIN * LDIM) return;
    int hw = i & 1023, bc = i >> 10;
    int h = hw >> 5, w = hw & 31;
    float r = fminf(fmaxf(inp[i], -1.0f), 1.0f);
    int base = (bc * 34 + (h + 1)) * 34 + (w + 1);
    const int astr = BATCH * CIN * 34 * 34;
    float half = 0.5f;
#pragma unroll
    for (int a = 0; a < ABITS; ++a) {
        bool pos = (r >= 0.0f);
        d_SP[a * astr + base] = pos ? 1 : -1;
        r = __fsub_rn(r, pos ? half : -half);
        half = __fmul_rn(half, 0.5f);
    }
}

// ---------------- kW: weight standardize + 4-bit quantize ------------------
__global__ void kW(const float* __restrict__ wgt) {
    int o = blockIdx.x;                 // 128
    int t = threadIdx.x;                // 64
    __shared__ double red[64], red2[64];
    __shared__ float s_mean, s_std;
    const float* wr = wgt + o * CKTOT;

    double s = 0.0;
    for (int i = t; i < CKTOT; i += 64) s += (double)wr[i];
    red[t] = s; __syncthreads();
    for (int st = 32; st; st >>= 1) { if (t < st) red[t] += red[t + st]; __syncthreads(); }
    if (!t) s_mean = (float)(red[0] / 576.0);
    __syncthreads();
    float mf = s_mean;

    double s1 = 0.0, s2 = 0.0;
    for (int i = t; i < CKTOT; i += 64) {
        float bw = __fsub_rn(wr[i], mf);
        s1 += (double)bw; s2 += (double)bw * (double)bw;
    }
    red[t] = s1; red2[t] = s2; __syncthreads();
    for (int st = 32; st; st >>= 1) {
        if (t < st) { red[t] += red[t + st]; red2[t] += red2[t + st]; }
        __syncthreads();
    }
    if (!t) {
        double mu = red[0] / 576.0;
        double var = (red2[0] - 576.0 * mu * mu) / 575.0;  // ddof=1
        s_std = (float)sqrt(var);
    }
    __syncthreads();
    float stdf = s_std;

    for (int i = t; i < CKTOT; i += 64) {
        float bw = __fsub_rn(wr[i], mf);
        float c = fminf(fmaxf(__fdiv_rn(bw, stdf), -1.0f), 1.0f);
        int m = (int)rintf(__fmul_rn(c, 7.0f));   // round-half-even, like jnp.round
        ((signed char*)d_Wp)[(((unsigned)i >> 2) * OUTC + o) * 4 + (i & 3)] = (signed char)m;
    }
}

// ---------------- kS2: pack unfolded sign bytes into dp4a words ------------
__global__ void kS2() {
    int idx = blockIdx.x * 256 + threadIdx.x;        // over 32*144*1024
    if (idx >= NTOT * 144 * LDIM) return;
    int l = idx & 1023;
    int rest = idx >> 10;                             // n*144 + q
    int q = rest % 144, n = rest / 144;
    int a = n >> 3, b = n & 7;
    int h = l >> 5, w = l & 31;
    unsigned word = 0;
#pragma unroll
    for (int s = 0; s < 4; ++s) {
        int ck = q * 4 + s;
        int c = ck / 9, kp = ck - 9 * c;
        int y = h + kp / 3, x = w + kp % 3;           // padded coords
        signed char sv = d_SP[(((a * 8 + b) * CIN + c) * 34 + y) * 34 + x];
        word |= ((unsigned)(unsigned char)sv) << (8 * s);
    }
    d_U4[idx] = (int)word;
}

// ---------------- kG: exact int8 GEMM (7*lt) via dp4a ----------------------
__global__ void __launch_bounds__(256) kG() {
    __shared__ __align__(16) int ws[OUTC][16];
    int g = blockIdx.y;
    for (int i = threadIdx.x; i < OUTC * 16; i += 256) {
        int o = i >> 4, q = i & 15;
        ws[o][q] = d_Wp[(16 * g + q) * OUTC + o];
    }
    __syncthreads();
    int p = blockIdx.x * 256 + threadIdx.x;           // 0..32767
    int n = p >> 10, l = p & 1023;
    int A[16];
    const int* ub = d_U4 + (n * 144 + 16 * g) * LDIM + l;
#pragma unroll
    for (int q = 0; q < 16; ++q) A[q] = ub[q * LDIM];
    short* tb = d_t7 + (((g * NTOT + n) << 17) >> 0) + l;   // (g*32+n)*128*1024 + l
    for (int o = 0; o < OUTC; ++o) {
        int acc = 0;
#pragma unroll
        for (int q4 = 0; q4 < 4; ++q4) {
            int4 wv = *(const int4*)&ws[o][q4 * 4];
            acc = __dp4a(A[q4 * 4 + 0], wv.x, acc);
            acc = __dp4a(A[q4 * 4 + 1], wv.y, acc);
            acc = __dp4a(A[q4 * 4 + 2], wv.z, acc);
            acc = __dp4a(A[q4 * 4 + 3], wv.w, acc);
        }
        tb[o << 10] = (short)acc;
    }
}

// ---------------- kStats: exact BN mean/var per (g,o) ----------------------
__global__ void kStats() {
    int go = blockIdx.x;            // 0..1151
    int g = go >> 7, o = go & 127;
    int t = threadIdx.x;            // 256
    const short* base = d_t7 + ((g * NTOT) << 17) + (o << 10);
    int s1 = 0; long long s2 = 0;
    for (int n = 0; n < NTOT; ++n) {
        const short* row = base + (n << 17);
        for (int l = t; l < LDIM; l += 256) {
            int m = row[l];
            s1 += m; s2 += (long long)(m * m);
        }
    }
    __shared__ int r1[256]; __shared__ long long r2[256];
    r1[t] = s1; r2[t] = s2; __syncthreads();
    for (int st = 128; st; st >>= 1) {
        if (t < st) { r1[t] += r1[t + st]; r2[t] += r2[t + st]; }
        __syncthreads();
    }
    if (!t) {
        double mu  = (double)r1[0] / (7.0 * 32768.0);
        double ex2 = (double)r2[0] / (49.0 * 32768.0);
        double var = ex2 - mu * mu;          // biased (BN train)
        d_Mean[go] = (float)mu;
        d_Sf[go]   = __fsqrt_rn(__fadd_rn((float)var, 1e-5f));
    }
}

// ---------------- kE: threefry + tanh + binarize + recombine ---------------
__global__ void __launch_bounds__(256) kE(const float* __restrict__ gamma,
                                          const float* __restrict__ beta,
                                          float* __restrict__ out, Keys keys) {
    int l = blockIdx.x * 256 + threadIdx.x;   // 0..1023
    int o = blockIdx.y;                        // 0..127
    int b = blockIdx.z;                        // 0..7
    float gam = gamma[o], bet = beta[o];
    int S[ABITS] = {0, 0, 0, 0};
    for (int g = 0; g < GCH; ++g) {
        float mn = d_Mean[g * OUTC + o];
        float sd = d_Sf[g * OUTC + o];
        unsigned kg0 = keys.v[2 * g], kg1 = keys.v[2 * g + 1];
#pragma unroll
        for (int a = 0; a < ABITS; ++a) {
            int n = a * 8 + b;
            int m7 = d_t7[(((g * NTOT + n) << 17)) + (o << 10) + l];
            float lt = __fdiv_rn(__int2float_rn(m7), 7.0f);
            float normed = __fadd_rn(__fmul_rn(__fdiv_rn(__fsub_rn(lt, mn), sd), gam), bet);
            float t = tanh_xla(__fmul_rn(normed, 4.0f));
            unsigned j = ((unsigned)(n * OUTC + o) << 10) + (unsigned)l;
            unsigned r0, r1; tf2x32(kg0, kg1, 0u, j, r0, r1);
            unsigned bits = r0 ^ r1;
            float u = __fsub_rn(__uint_as_float((bits >> 9) | 0x3f800000u), 1.0f);
            float rnd = __fadd_rn(__fmul_rn(u, 2.0f), -1.0f);
            int s = (normed == 0.0f) ? 0 : ((t > rnd) ? 1 : -1);
            S[a] += s;
        }
    }
    const float wts[ABITS] = {0.5f, 0.25f, 0.125f, 0.0625f};
    float acc = 0.0f;
#pragma unroll
    for (int a = 0; a < ABITS; ++a)
        acc = __fadd_rn(acc, __fmul_rn(__fdiv_rn((float)S[a], 9.0f), wts[a]));
    out[((b * OUTC + o) << 10) + l] = acc;
}

// ---------------------------------------------------------------------------
extern "C" void kernel_launch(void* const* d_in, const int* in_sizes, int n_in,
                              void* d_out, int out_size) {
    const float* inp   = (const float*)d_in[0];   // [8,64,32,32]
    const float* wgt   = (const float*)d_in[1];   // [128,64,3,3]
    const float* gamma = (const float*)d_in[2];   // [128]
    const float* beta  = (const float*)d_in[3];   // [128]
    float* out = (float*)d_out;                   // [8,128,32,32]

    // host-side key derivation: keys = split(key(42), 9) in partitionable mode
    Keys ks;
    for (int g = 0; g < GCH; ++g) {
        unsigned o0, o1;
        tf2x32(0u, 42u, 0u, (unsigned)g, o0, o1);
        ks.v[2 * g] = o0; ks.v[2 * g + 1] = o1;
    }

    const int spTot = ABITS * BATCH * CIN * 34 * 34;
    kFill<<<(spTot + 255) / 256, 256>>>();
    kS1<<<(BATCH * CIN * LDIM + 255) / 256, 256>>>(inp);
    kW<<<OUTC, 64>>>(wgt);
    kS2<<<(NTOT * 144 * LDIM + 255) / 256, 256>>>();
    kG<<<dim3(128, GCH), 256>>>();
    kStats<<<GCH * OUTC, 256>>>();
    kE<<<dim3(4, OUTC, BATCH), 256>>>(gamma, beta, out, ks);
}

// round 9
// speedup vs baseline: 1.4319x; 1.4319x over previous
#include <cuda_runtime.h>
#include <cstdint>

// ---------------------------------------------------------------------------
// StoX_Conv2d: 4-bit-weight / 4-plane-binarized-activation conv + per-chunk
// BatchNorm + stochastic MTJ binarization (exact JAX threefry reproduction).
// R8: fused unfold+GEMM, tabulated tanh/BN path, merged prep.
// ---------------------------------------------------------------------------

#define BATCH 8
#define CIN   64
#define LDIM  1024          // 32*32
#define OUTC  128
#define ABITS 4
#define GCH   9             // NUM_CHUNKS
#define CKTOT 576           // CIN*9
#define NTOT  32            // ABITS*BATCH
#define PSTR  1160          // padded 34x34 plane stride (1156 -> 1160, word aligned)
#define TROW  904           // table row stride (897 entries padded)

// ---- static device scratch (allocation-free rule: __device__ globals) -----
__device__ __align__(16) signed char d_SP[NTOT * CIN * PSTR];        // padded sign planes
__device__ __align__(16) int         d_Wp[144 * OUTC];               // packed quantized weights *7
__device__ __align__(16) short       d_t7[GCH * NTOT * OUTC * LDIM]; // 7*lt exact int
__device__ float                     d_Mean[GCH * OUTC];
__device__ float                     d_Sf[GCH * OUTC];               // sqrt(var+eps)
__device__ __align__(16) float       d_T[GCH * OUTC * TROW];         // tanh table

struct Keys { unsigned v[2 * GCH]; };

// ---------------- Threefry2x32 (matches jax/_src/prng.py bit-exactly) ------
__host__ __device__ __forceinline__ unsigned rotl32(unsigned x, int r) {
#if defined(__CUDA_ARCH__)
    return __funnelshift_l(x, x, r);
#else
    return (x << r) | (x >> (32 - r));
#endif
}

__host__ __device__ __forceinline__ void tf2x32(unsigned k0, unsigned k1,
                                                unsigned x0, unsigned x1,
                                                unsigned& o0, unsigned& o1) {
    unsigned k2 = k0 ^ k1 ^ 0x1BD11BDAu;
    x0 += k0; x1 += k1;
#define TF_R(r) { x0 += x1; x1 = rotl32(x1, r); x1 ^= x0; }
    TF_R(13) TF_R(15) TF_R(26) TF_R(6)
    x0 += k1; x1 += k2 + 1u;
    TF_R(17) TF_R(29) TF_R(16) TF_R(24)
    x0 += k2; x1 += k0 + 2u;
    TF_R(13) TF_R(15) TF_R(26) TF_R(6)
    x0 += k0; x1 += k1 + 3u;
    TF_R(17) TF_R(29) TF_R(16) TF_R(24)
    x0 += k1; x1 += k2 + 4u;
    TF_R(13) TF_R(15) TF_R(26) TF_R(6)
    x0 += k2; x1 += k0 + 5u;
#undef TF_R
    o0 = x0; o1 = x1;
}

// ---------------- XLA EmitTanh f32 rational (un-fused mul/add) -------------
__device__ __forceinline__ float tanh_xla(float xin) {
    float x = fminf(fmaxf(xin, -9.0f), 9.0f);
    float x2 = __fmul_rn(x, x);
    float p = -2.76076847742355e-16f;
    p = __fadd_rn(__fmul_rn(x2, p),  2.00018790482477e-13f);
    p = __fadd_rn(__fmul_rn(x2, p), -8.60467152213735e-11f);
    p = __fadd_rn(__fmul_rn(x2, p),  5.12229709037114e-08f);
    p = __fadd_rn(__fmul_rn(x2, p),  1.48572235717979e-05f);
    p = __fadd_rn(__fmul_rn(x2, p),  6.37261928875436e-04f);
    p = __fadd_rn(__fmul_rn(x2, p),  4.89352455891786e-03f);
    float num = __fmul_rn(x, p);
    float q = 1.19825839466702e-06f;
    q = __fadd_rn(__fmul_rn(x2, q), 1.18534705686654e-04f);
    q = __fadd_rn(__fmul_rn(x2, q), 2.26843463243900e-03f);
    q = __fadd_rn(__fmul_rn(x2, q), 4.89352518554385e-03f);
    float r = __fdiv_rn(num, q);
    return (fabsf(xin) < 0.0004f) ? xin : r;
}

// ---------------- kPrep: sign planes (fill + interior in one pass) ---------
__global__ void kPrep(const float* __restrict__ inp) {
    int i = blockIdx.x * 256 + threadIdx.x;         // over 512*1156
    if (i >= BATCH * CIN * 1156) return;
    int bc = i / 1156, p = i - bc * 1156;
    int y = p / 34, x = p - y * 34;
    const int AS = 512 * PSTR;                      // a-plane stride
    int base = bc * PSTR + p;
    if (y == 0 || y == 33 || x == 0 || x == 33) {
        d_SP[base] = 1;
        d_SP[AS + base] = -1;
        d_SP[2 * AS + base] = -1;
        d_SP[3 * AS + base] = -1;
    } else {
        float v = inp[(bc << 10) + (y - 1) * 32 + (x - 1)];
        float r = fminf(fmaxf(v, -1.0f), 1.0f);
        float half = 0.5f;
#pragma unroll
        for (int a = 0; a < ABITS; ++a) {
            bool pos = (r >= 0.0f);
            d_SP[a * AS + base] = pos ? 1 : -1;
            r = __fsub_rn(r, pos ? half : -half);
            half = __fmul_rn(half, 0.5f);
        }
    }
}

// ---------------- kW: weight standardize + 4-bit quantize ------------------
__global__ void kW(const float* __restrict__ wgt) {
    int o = blockIdx.x;                 // 128
    int t = threadIdx.x;                // 64
    __shared__ double red[64], red2[64];
    __shared__ float s_mean, s_std;
    const float* wr = wgt + o * CKTOT;

    double s = 0.0;
    for (int i = t; i < CKTOT; i += 64) s += (double)wr[i];
    red[t] = s; __syncthreads();
    for (int st = 32; st; st >>= 1) { if (t < st) red[t] += red[t + st]; __syncthreads(); }
    if (!t) s_mean = (float)(red[0] / 576.0);
    __syncthreads();
    float mf = s_mean;

    double s1 = 0.0, s2 = 0.0;
    for (int i = t; i < CKTOT; i += 64) {
        float bw = __fsub_rn(wr[i], mf);
        s1 += (double)bw; s2 += (double)bw * (double)bw;
    }
    red[t] = s1; red2[t] = s2; __syncthreads();
    for (int st = 32; st; st >>= 1) {
        if (t < st) { red[t] += red[t + st]; red2[t] += red2[t + st]; }
        __syncthreads();
    }
    if (!t) {
        double mu = red[0] / 576.0;
        double var = (red2[0] - 576.0 * mu * mu) / 575.0;  // ddof=1
        s_std = (float)sqrt(var);
    }
    __syncthreads();
    float stdf = s_std;

    for (int i = t; i < CKTOT; i += 64) {
        float bw = __fsub_rn(wr[i], mf);
        float c = fminf(fmaxf(__fdiv_rn(bw, stdf), -1.0f), 1.0f);
        int m = (int)rintf(__fmul_rn(c, 7.0f));   // round-half-even, like jnp.round
        ((signed char*)d_Wp)[(((unsigned)i >> 2) * OUTC + o) * 4 + (i & 3)] = (signed char)m;
    }
}

// ---------------- kG: fused unfold + exact int8 GEMM (7*lt) ----------------
// grid (2 l-halves, 32 n, 9 g), 256 threads; each thread handles 2 l's.
__global__ void __launch_bounds__(256) kG() {
    __shared__ __align__(16) int ws[OUTC][16];
    __shared__ __align__(16) signed char sgn[9 * PSTR];   // <= 9 channels
    int g = blockIdx.z, n = blockIdx.y, lh = blockIdx.x;
    int tid = threadIdx.x;

    for (int i = tid; i < OUTC * 16; i += 256) {
        int o = i >> 4, q = i & 15;
        ws[o][q] = d_Wp[(16 * g + q) * OUTC + o];
    }
    int c_lo = (64 * g) / 9;
    int cn = min(9, CIN - c_lo);
    {
        const int* src = (const int*)(d_SP + (n * CIN + c_lo) * PSTR);
        int* dst = (int*)sgn;
        int words = cn * (PSTR / 4);
        for (int i = tid; i < words; i += 256) dst[i] = src[i];
    }
    __syncthreads();

    int l0 = lh * 512 + tid;
    int l1 = l0 + 256;
    int px0 = (l0 >> 5) * 34 + (l0 & 31);
    int px1 = (l1 >> 5) * 34 + (l1 & 31);

    int A0[16], A1[16];
#pragma unroll
    for (int q = 0; q < 16; ++q) { A0[q] = 0; A1[q] = 0; }
#pragma unroll
    for (int q = 0; q < 16; ++q) {
#pragma unroll
        for (int s = 0; s < 4; ++s) {
            int ck = 64 * g + q * 4 + s;
            int cq = ck / 9;
            int kp = ck - cq * 9;
            int dy = kp / 3, dx = kp - dy * 3;
            int boff = (cq - c_lo) * PSTR + dy * 34 + dx;   // block-uniform
            unsigned b0 = (unsigned char)sgn[boff + px0];
            unsigned b1 = (unsigned char)sgn[boff + px1];
            A0[q] |= b0 << (8 * s);
            A1[q] |= b1 << (8 * s);
        }
    }

    short* tb = d_t7 + ((g * NTOT + n) << 17) + l0;
    for (int o = 0; o < OUTC; ++o) {
        int a0 = 0, a1 = 0;
#pragma unroll
        for (int q4 = 0; q4 < 4; ++q4) {
            int4 wv = *(const int4*)&ws[o][q4 * 4];
            a0 = __dp4a(A0[q4 * 4 + 0], wv.x, a0); a1 = __dp4a(A1[q4 * 4 + 0], wv.x, a1);
            a0 = __dp4a(A0[q4 * 4 + 1], wv.y, a0); a1 = __dp4a(A1[q4 * 4 + 1], wv.y, a1);
            a0 = __dp4a(A0[q4 * 4 + 2], wv.z, a0); a1 = __dp4a(A1[q4 * 4 + 2], wv.z, a1);
            a0 = __dp4a(A0[q4 * 4 + 3], wv.w, a0); a1 = __dp4a(A1[q4 * 4 + 3], wv.w, a1);
        }
        tb[o << 10] = (short)a0;
        tb[(o << 10) + 256] = (short)a1;
    }
}

// ---------------- kStats: exact BN mean/var per (g,o) ----------------------
__global__ void kStats() {
    int go = blockIdx.x;            // 0..1151
    int g = go >> 7, o = go & 127;
    int t = threadIdx.x;            // 256
    const short* base = d_t7 + ((g * NTOT) << 17) + (o << 10);
    int s1 = 0; long long s2 = 0;
    for (int n = 0; n < NTOT; ++n) {
        const int* row = (const int*)(base + (n << 17));
        for (int w = t; w < 512; w += 256) {
            int v = row[w];
            int mA = (short)(v & 0xFFFF);
            int mB = (v >> 16);
            s1 += mA + mB;
            s2 += (long long)(mA * mA + mB * mB);
        }
    }
    __shared__ int r1[256]; __shared__ long long r2[256];
    r1[t] = s1; r2[t] = s2; __syncthreads();
    for (int st = 128; st; st >>= 1) {
        if (t < st) { r1[t] += r1[t + st]; r2[t] += r2[t + st]; }
        __syncthreads();
    }
    if (!t) {
        double mu  = (double)r1[0] / (7.0 * 32768.0);
        double ex2 = (double)r2[0] / (49.0 * 32768.0);
        double var = ex2 - mu * mu;          // biased (BN train)
        d_Mean[go] = (float)mu;
        d_Sf[go]   = __fsqrt_rn(__fadd_rn((float)var, 1e-5f));
    }
}

// ---------------- kT: tabulate t = tanh_xla(4*normed(m7)) per (g,o) --------
// Bit-identical op sequence to the previously-passing per-element path.
__global__ void kT(const float* __restrict__ gamma, const float* __restrict__ beta) {
    int go = blockIdx.x;               // 0..1151
    int g = go >> 7, o = go & 127; (void)g;
    float mn = d_Mean[go], sd = d_Sf[go];
    float gam = gamma[o], bet = beta[o];
    for (int idx = threadIdx.x; idx < 897; idx += 256) {
        float lt = __fdiv_rn(__int2float_rn(idx - 448), 7.0f);
        float normed = __fadd_rn(__fmul_rn(__fdiv_rn(__fsub_rn(lt, mn), sd), gam), bet);
        float t = tanh_xla(__fmul_rn(normed, 4.0f));
        d_T[go * TROW + idx] = t;
    }
}

// ---------------- kE: threefry + table lookup + binarize + recombine -------
__global__ void __launch_bounds__(256) kE(float* __restrict__ out, Keys keys) {
    __shared__ float tt[GCH][TROW];
    int l = blockIdx.x * 256 + threadIdx.x;    // 0..1023
    int o = blockIdx.y;                         // 0..127
    int b = blockIdx.z;                         // 0..7
#pragma unroll
    for (int g = 0; g < GCH; ++g)
        for (int idx = threadIdx.x; idx < 897; idx += 256)
            tt[g][idx] = d_T[(g * OUTC + o) * TROW + idx];
    __syncthreads();

    int S[ABITS] = {0, 0, 0, 0};
#pragma unroll 1
    for (int g = 0; g < GCH; ++g) {
        unsigned k0 = keys.v[2 * g], k1 = keys.v[2 * g + 1];
#pragma unroll
        for (int a = 0; a < ABITS; ++a) {
            int n = a * 8 + b;
            int m7 = d_t7[((g * NTOT + n) << 17) + (o << 10) + l];
            float t = tt[g][m7 + 448];
            unsigned j = ((unsigned)(n * OUTC + o) << 10) + (unsigned)l;
            unsigned r0, r1; tf2x32(k0, k1, 0u, j, r0, r1);
            unsigned bits = r0 ^ r1;
            float u = __fsub_rn(__uint_as_float((bits >> 9) | 0x3f800000u), 1.0f);
            float rnd = __fadd_rn(__fmul_rn(u, 2.0f), -1.0f);
            int s = (t > rnd) ? 1 : -1;
            s = (t == 0.0f) ? 0 : s;      // normed==0 <=> t==+-0 (tanh_xla small-x path)
            S[a] += s;
        }
    }
    const float wts[ABITS] = {0.5f, 0.25f, 0.125f, 0.0625f};
    float acc = 0.0f;
#pragma unroll
    for (int a = 0; a < ABITS; ++a)
        acc = __fadd_rn(acc, __fmul_rn(__fdiv_rn((float)S[a], 9.0f), wts[a]));
    out[((b * OUTC + o) << 10) + l] = acc;
}

// ---------------------------------------------------------------------------
extern "C" void kernel_launch(void* const* d_in, const int* in_sizes, int n_in,
                              void* d_out, int out_size) {
    const float* inp   = (const float*)d_in[0];   // [8,64,32,32]
    const float* wgt   = (const float*)d_in[1];   // [128,64,3,3]
    const float* gamma = (const float*)d_in[2];   // [128]
    const float* beta  = (const float*)d_in[3];   // [128]
    float* out = (float*)d_out;                   // [8,128,32,32]

    // host-side key derivation: keys = split(key(42), 9) in partitionable mode
    Keys ks;
    for (int g = 0; g < GCH; ++g) {
        unsigned o0, o1;
        tf2x32(0u, 42u, 0u, (unsigned)g, o0, o1);
        ks.v[2 * g] = o0; ks.v[2 * g + 1] = o1;
    }

    kPrep<<<(BATCH * CIN * 1156 + 255) / 256, 256>>>(inp);
    kW<<<OUTC, 64>>>(wgt);
    kG<<<dim3(2, NTOT, GCH), 256>>>();
    kStats<<<GCH * OUTC, 256>>>();
    kT<<<GCH * OUTC, 256>>>(gamma, beta);
    kE<<<dim3(4, OUTC, BATCH), 256>>>(out, ks);
}

// round 10
// speedup vs baseline: 1.4403x; 1.0058x over previous
#include <cuda_runtime.h>
#include <cstdint>

// ---------------------------------------------------------------------------
// StoX_Conv2d: 4-bit-weight / 4-plane-binarized-activation conv + per-chunk
// BatchNorm + stochastic MTJ binarization (exact JAX threefry reproduction).
// R8: fused unfold+GEMM, tabulated tanh/BN path, merged prep.
// ---------------------------------------------------------------------------

#define BATCH 8
#define CIN   64
#define LDIM  1024          // 32*32
#define OUTC  128
#define ABITS 4
#define GCH   9             // NUM_CHUNKS
#define CKTOT 576           // CIN*9
#define NTOT  32            // ABITS*BATCH
#define PSTR  1160          // padded 34x34 plane stride (1156 -> 1160, word aligned)
#define TROW  904           // table row stride (897 entries padded)

// ---- static device scratch (allocation-free rule: __device__ globals) -----
__device__ __align__(16) signed char d_SP[NTOT * CIN * PSTR];        // padded sign planes
__device__ __align__(16) int         d_Wp[144 * OUTC];               // packed quantized weights *7
__device__ __align__(16) short       d_t7[GCH * NTOT * OUTC * LDIM]; // 7*lt exact int
__device__ float                     d_Mean[GCH * OUTC];
__device__ float                     d_Sf[GCH * OUTC];               // sqrt(var+eps)
__device__ __align__(16) float       d_T[GCH * OUTC * TROW];         // tanh table

struct Keys { unsigned v[2 * GCH]; };

// ---------------- Threefry2x32 (matches jax/_src/prng.py bit-exactly) ------
__host__ __device__ __forceinline__ unsigned rotl32(unsigned x, int r) {
#if defined(__CUDA_ARCH__)
    return __funnelshift_l(x, x, r);
#else
    return (x << r) | (x >> (32 - r));
#endif
}

__host__ __device__ __forceinline__ void tf2x32(unsigned k0, unsigned k1,
                                                unsigned x0, unsigned x1,
                                                unsigned& o0, unsigned& o1) {
    unsigned k2 = k0 ^ k1 ^ 0x1BD11BDAu;
    x0 += k0; x1 += k1;
#define TF_R(r) { x0 += x1; x1 = rotl32(x1, r); x1 ^= x0; }
    TF_R(13) TF_R(15) TF_R(26) TF_R(6)
    x0 += k1; x1 += k2 + 1u;
    TF_R(17) TF_R(29) TF_R(16) TF_R(24)
    x0 += k2; x1 += k0 + 2u;
    TF_R(13) TF_R(15) TF_R(26) TF_R(6)
    x0 += k0; x1 += k1 + 3u;
    TF_R(17) TF_R(29) TF_R(16) TF_R(24)
    x0 += k1; x1 += k2 + 4u;
    TF_R(13) TF_R(15) TF_R(26) TF_R(6)
    x0 += k2; x1 += k0 + 5u;
#undef TF_R
    o0 = x0; o1 = x1;
}

// ---------------- XLA EmitTanh f32 rational (un-fused mul/add) -------------
__device__ __forceinline__ float tanh_xla(float xin) {
    float x = fminf(fmaxf(xin, -9.0f), 9.0f);
    float x2 = __fmul_rn(x, x);
    float p = -2.76076847742355e-16f;
    p = __fadd_rn(__fmul_rn(x2, p),  2.00018790482477e-13f);
    p = __fadd_rn(__fmul_rn(x2, p), -8.60467152213735e-11f);
    p = __fadd_rn(__fmul_rn(x2, p),  5.12229709037114e-08f);
    p = __fadd_rn(__fmul_rn(x2, p),  1.48572235717979e-05f);
    p = __fadd_rn(__fmul_rn(x2, p),  6.37261928875436e-04f);
    p = __fadd_rn(__fmul_rn(x2, p),  4.89352455891786e-03f);
    float num = __fmul_rn(x, p);
    float q = 1.19825839466702e-06f;
    q = __fadd_rn(__fmul_rn(x2, q), 1.18534705686654e-04f);
    q = __fadd_rn(__fmul_rn(x2, q), 2.26843463243900e-03f);
    q = __fadd_rn(__fmul_rn(x2, q), 4.89352518554385e-03f);
    float r = __fdiv_rn(num, q);
    return (fabsf(xin) < 0.0004f) ? xin : r;
}

// ---------------- kPrep: sign planes (fill + interior in one pass) ---------
__global__ void kPrep(const float* __restrict__ inp) {
    int i = blockIdx.x * 256 + threadIdx.x;         // over 512*1156
    if (i >= BATCH * CIN * 1156) return;
    int bc = i / 1156, p = i - bc * 1156;
    int y = p / 34, x = p - y * 34;
    const int AS = 512 * PSTR;                      // a-plane stride
    int base = bc * PSTR + p;
    if (y == 0 || y == 33 || x == 0 || x == 33) {
        d_SP[base] = 1;
        d_SP[AS + base] = -1;
        d_SP[2 * AS + base] = -1;
        d_SP[3 * AS + base] = -1;
    } else {
        float v = inp[(bc << 10) + (y - 1) * 32 + (x - 1)];
        float r = fminf(fmaxf(v, -1.0f), 1.0f);
        float half = 0.5f;
#pragma unroll
        for (int a = 0; a < ABITS; ++a) {
            bool pos = (r >= 0.0f);
            d_SP[a * AS + base] = pos ? 1 : -1;
            r = __fsub_rn(r, pos ? half : -half);
            half = __fmul_rn(half, 0.5f);
        }
    }
}

// ---------------- kW: weight standardize + 4-bit quantize ------------------
__global__ void kW(const float* __restrict__ wgt) {
    int o = blockIdx.x;                 // 128
    int t = threadIdx.x;                // 64
    __shared__ double red[64], red2[64];
    __shared__ float s_mean, s_std;
    const float* wr = wgt + o * CKTOT;

    double s = 0.0;
    for (int i = t; i < CKTOT; i += 64) s += (double)wr[i];
    red[t] = s; __syncthreads();
    for (int st = 32; st; st >>= 1) { if (t < st) red[t] += red[t + st]; __syncthreads(); }
    if (!t) s_mean = (float)(red[0] / 576.0);
    __syncthreads();
    float mf = s_mean;

    double s1 = 0.0, s2 = 0.0;
    for (int i = t; i < CKTOT; i += 64) {
        float bw = __fsub_rn(wr[i], mf);
        s1 += (double)bw; s2 += (double)bw * (double)bw;
    }
    red[t] = s1; red2[t] = s2; __syncthreads();
    for (int st = 32; st; st >>= 1) {
        if (t < st) { red[t] += red[t + st]; red2[t] += red2[t + st]; }
        __syncthreads();
    }
    if (!t) {
        double mu = red[0] / 576.0;
        double var = (red2[0] - 576.0 * mu * mu) / 575.0;  // ddof=1
        s_std = (float)sqrt(var);
    }
    __syncthreads();
    float stdf = s_std;

    for (int i = t; i < CKTOT; i += 64) {
        float bw = __fsub_rn(wr[i], mf);
        float c = fminf(fmaxf(__fdiv_rn(bw, stdf), -1.0f), 1.0f);
        int m = (int)rintf(__fmul_rn(c, 7.0f));   // round-half-even, like jnp.round
        ((signed char*)d_Wp)[(((unsigned)i >> 2) * OUTC + o) * 4 + (i & 3)] = (signed char)m;
    }
}

// ---------------- kG: fused unfold + exact int8 GEMM (7*lt) ----------------
// grid (2 l-halves, 32 n, 9 g), 256 threads; each thread handles 2 l's.
__global__ void __launch_bounds__(256) kG() {
    __shared__ __align__(16) int ws[OUTC][16];
    __shared__ __align__(16) signed char sgn[9 * PSTR];   // <= 9 channels
    int g = blockIdx.z, n = blockIdx.y, lh = blockIdx.x;
    int tid = threadIdx.x;

    for (int i = tid; i < OUTC * 16; i += 256) {
        int o = i >> 4, q = i & 15;
        ws[o][q] = d_Wp[(16 * g + q) * OUTC + o];
    }
    int c_lo = (64 * g) / 9;
    int cn = min(9, CIN - c_lo);
    {
        const int* src = (const int*)(d_SP + (n * CIN + c_lo) * PSTR);
        int* dst = (int*)sgn;
        int words = cn * (PSTR / 4);
        for (int i = tid; i < words; i += 256) dst[i] = src[i];
    }
    __syncthreads();

    int l0 = lh * 512 + tid;
    int l1 = l0 + 256;
    int px0 = (l0 >> 5) * 34 + (l0 & 31);
    int px1 = (l1 >> 5) * 34 + (l1 & 31);

    int A0[16], A1[16];
#pragma unroll
    for (int q = 0; q < 16; ++q) { A0[q] = 0; A1[q] = 0; }
#pragma unroll
    for (int q = 0; q < 16; ++q) {
#pragma unroll
        for (int s = 0; s < 4; ++s) {
            int ck = 64 * g + q * 4 + s;
            int cq = ck / 9;
            int kp = ck - cq * 9;
            int dy = kp / 3, dx = kp - dy * 3;
            int boff = (cq - c_lo) * PSTR + dy * 34 + dx;   // block-uniform
            unsigned b0 = (unsigned char)sgn[boff + px0];
            unsigned b1 = (unsigned char)sgn[boff + px1];
            A0[q] |= b0 << (8 * s);
            A1[q] |= b1 << (8 * s);
        }
    }

    short* tb = d_t7 + ((g * NTOT + n) << 17) + l0;
    for (int o = 0; o < OUTC; ++o) {
        int a0 = 0, a1 = 0;
#pragma unroll
        for (int q4 = 0; q4 < 4; ++q4) {
            int4 wv = *(const int4*)&ws[o][q4 * 4];
            a0 = __dp4a(A0[q4 * 4 + 0], wv.x, a0); a1 = __dp4a(A1[q4 * 4 + 0], wv.x, a1);
            a0 = __dp4a(A0[q4 * 4 + 1], wv.y, a0); a1 = __dp4a(A1[q4 * 4 + 1], wv.y, a1);
            a0 = __dp4a(A0[q4 * 4 + 2], wv.z, a0); a1 = __dp4a(A1[q4 * 4 + 2], wv.z, a1);
            a0 = __dp4a(A0[q4 * 4 + 3], wv.w, a0); a1 = __dp4a(A1[q4 * 4 + 3], wv.w, a1);
        }
        tb[o << 10] = (short)a0;
        tb[(o << 10) + 256] = (short)a1;
    }
}

// ---------------- kStats: exact BN mean/var per (g,o) ----------------------
__global__ void kStats() {
    int go = blockIdx.x;            // 0..1151
    int g = go >> 7, o = go & 127;
    int t = threadIdx.x;            // 256
    const short* base = d_t7 + ((g * NTOT) << 17) + (o << 10);
    int s1 = 0; long long s2 = 0;
    for (int n = 0; n < NTOT; ++n) {
        const int* row = (const int*)(base + (n << 17));
        for (int w = t; w < 512; w += 256) {
            int v = row[w];
            int mA = (short)(v & 0xFFFF);
            int mB = (v >> 16);
            s1 += mA + mB;
            s2 += (long long)(mA * mA + mB * mB);
        }
    }
    __shared__ int r1[256]; __shared__ long long r2[256];
    r1[t] = s1; r2[t] = s2; __syncthreads();
    for (int st = 128; st; st >>= 1) {
        if (t < st) { r1[t] += r1[t + st]; r2[t] += r2[t + st]; }
        __syncthreads();
    }
    if (!t) {
        double mu  = (double)r1[0] / (7.0 * 32768.0);
        double ex2 = (double)r2[0] / (49.0 * 32768.0);
        double var = ex2 - mu * mu;          // biased (BN train)
        d_Mean[go] = (float)mu;
        d_Sf[go]   = __fsqrt_rn(__fadd_rn((float)var, 1e-5f));
    }
}

// ---------------- kT: tabulate t = tanh_xla(4*normed(m7)) per (g,o) --------
// Bit-identical op sequence to the previously-passing per-element path.
__global__ void kT(const float* __restrict__ gamma, const float* __restrict__ beta) {
    int go = blockIdx.x;               // 0..1151
    int g = go >> 7, o = go & 127; (void)g;
    float mn = d_Mean[go], sd = d_Sf[go];
    float gam = gamma[o], bet = beta[o];
    for (int idx = threadIdx.x; idx < 897; idx += 256) {
        float lt = __fdiv_rn(__int2float_rn(idx - 448), 7.0f);
        float normed = __fadd_rn(__fmul_rn(__fdiv_rn(__fsub_rn(lt, mn), sd), gam), bet);
        float t = tanh_xla(__fmul_rn(normed, 4.0f));
        d_T[go * TROW + idx] = t;
    }
}

// ---------------- kE: threefry + table lookup + binarize + recombine -------
__global__ void __launch_bounds__(256) kE(float* __restrict__ out, Keys keys) {
    __shared__ float tt[GCH][TROW];
    int l = blockIdx.x * 256 + threadIdx.x;    // 0..1023
    int o = blockIdx.y;                         // 0..127
    int b = blockIdx.z;                         // 0..7
#pragma unroll
    for (int g = 0; g < GCH; ++g)
        for (int idx = threadIdx.x; idx < 897; idx += 256)
            tt[g][idx] = d_T[(g * OUTC + o) * TROW + idx];
    __syncthreads();

    int S[ABITS] = {0, 0, 0, 0};
#pragma unroll 1
    for (int g = 0; g < GCH; ++g) {
        unsigned k0 = keys.v[2 * g], k1 = keys.v[2 * g + 1];
#pragma unroll
        for (int a = 0; a < ABITS; ++a) {
            int n = a * 8 + b;
            int m7 = d_t7[((g * NTOT + n) << 17) + (o << 10) + l];
            float t = tt[g][m7 + 448];
            unsigned j = ((unsigned)(n * OUTC + o) << 10) + (unsigned)l;
            unsigned r0, r1; tf2x32(k0, k1, 0u, j, r0, r1);
            unsigned bits = r0 ^ r1;
            float u = __fsub_rn(__uint_as_float((bits >> 9) | 0x3f800000u), 1.0f);
            float rnd = __fadd_rn(__fmul_rn(u, 2.0f), -1.0f);
            int s = (t > rnd) ? 1 : -1;
            s = (t == 0.0f) ? 0 : s;      // normed==0 <=> t==+-0 (tanh_xla small-x path)
            S[a] += s;
        }
    }
    const float wts[ABITS] = {0.5f, 0.25f, 0.125f, 0.0625f};
    float acc = 0.0f;
#pragma unroll
    for (int a = 0; a < ABITS; ++a)
        acc = __fadd_rn(acc, __fmul_rn(__fdiv_rn((float)S[a], 9.0f), wts[a]));
    out[((b * OUTC + o) << 10) + l] = acc;
}

// ---------------------------------------------------------------------------
extern "C" void kernel_launch(void* const* d_in, const int* in_sizes, int n_in,
                              void* d_out, int out_size) {
    const float* inp   = (const float*)d_in[0];   // [8,64,32,32]
    const float* wgt   = (const float*)d_in[1];   // [128,64,3,3]
    const float* gamma = (const float*)d_in[2];   // [128]
    const float* beta  = (const float*)d_in[3];   // [128]
    float* out = (float*)d_out;                   // [8,128,32,32]

    // host-side key derivation: keys = split(key(42), 9) in partitionable mode
    Keys ks;
    for (int g = 0; g < GCH; ++g) {
        unsigned o0, o1;
        tf2x32(0u, 42u, 0u, (unsigned)g, o0, o1);
        ks.v[2 * g] = o0; ks.v[2 * g + 1] = o1;
    }

    kPrep<<<(BATCH * CIN * 1156 + 255) / 256, 256>>>(inp);
    kW<<<OUTC, 64>>>(wgt);
    kG<<<dim3(2, NTOT, GCH), 256>>>();
    kStats<<<GCH * OUTC, 256>>>();
    kT<<<GCH * OUTC, 256>>>(gamma, beta);
    kE<<<dim3(4, OUTC, BATCH), 256>>>(out, ks);
}

// round 11
// speedup vs baseline: 1.6216x; 1.1259x over previous
#include <cuda_runtime.h>
#include <cstdint>

// ---------------------------------------------------------------------------
// StoX_Conv2d: 4-bit-weight / 4-plane-binarized-activation conv + per-chunk
// BatchNorm + stochastic MTJ binarization (exact JAX threefry reproduction).
// R10: high-MLP atomic kStats, finalize fused into kT, 1024-thread kE.
// ---------------------------------------------------------------------------

#define BATCH 8
#define CIN   64
#define LDIM  1024          // 32*32
#define OUTC  128
#define ABITS 4
#define GCH   9             // NUM_CHUNKS
#define CKTOT 576           // CIN*9
#define NTOT  32            // ABITS*BATCH
#define PSTR  1160          // padded 34x34 plane stride (1156 -> 1160, word aligned)
#define TROW  904           // table row stride (897 entries padded)

// ---- static device scratch (allocation-free rule: __device__ globals) -----
__device__ __align__(16) signed char d_SP[NTOT * CIN * PSTR];        // padded sign planes
__device__ __align__(16) int         d_Wp[144 * OUTC];               // packed quantized weights *7
__device__ __align__(16) short       d_t7[GCH * NTOT * OUTC * LDIM]; // 7*lt exact int
__device__ int                       d_S1[GCH * OUTC];               // exact sum(m)
__device__ unsigned long long        d_S2[GCH * OUTC];               // exact sum(m^2)
__device__ __align__(16) float       d_T[GCH * OUTC * TROW];         // tanh table

struct Keys { unsigned v[2 * GCH]; };

// ---------------- Threefry2x32 (matches jax/_src/prng.py bit-exactly) ------
__host__ __device__ __forceinline__ unsigned rotl32(unsigned x, int r) {
#if defined(__CUDA_ARCH__)
    return __funnelshift_l(x, x, r);
#else
    return (x << r) | (x >> (32 - r));
#endif
}

__host__ __device__ __forceinline__ void tf2x32(unsigned k0, unsigned k1,
                                                unsigned x0, unsigned x1,
                                                unsigned& o0, unsigned& o1) {
    unsigned k2 = k0 ^ k1 ^ 0x1BD11BDAu;
    x0 += k0; x1 += k1;
#define TF_R(r) { x0 += x1; x1 = rotl32(x1, r); x1 ^= x0; }
    TF_R(13) TF_R(15) TF_R(26) TF_R(6)
    x0 += k1; x1 += k2 + 1u;
    TF_R(17) TF_R(29) TF_R(16) TF_R(24)
    x0 += k2; x1 += k0 + 2u;
    TF_R(13) TF_R(15) TF_R(26) TF_R(6)
    x0 += k0; x1 += k1 + 3u;
    TF_R(17) TF_R(29) TF_R(16) TF_R(24)
    x0 += k1; x1 += k2 + 4u;
    TF_R(13) TF_R(15) TF_R(26) TF_R(6)
    x0 += k2; x1 += k0 + 5u;
#undef TF_R
    o0 = x0; o1 = x1;
}

// ---------------- XLA EmitTanh f32 rational (un-fused mul/add) -------------
__device__ __forceinline__ float tanh_xla(float xin) {
    float x = fminf(fmaxf(xin, -9.0f), 9.0f);
    float x2 = __fmul_rn(x, x);
    float p = -2.76076847742355e-16f;
    p = __fadd_rn(__fmul_rn(x2, p),  2.00018790482477e-13f);
    p = __fadd_rn(__fmul_rn(x2, p), -8.60467152213735e-11f);
    p = __fadd_rn(__fmul_rn(x2, p),  5.12229709037114e-08f);
    p = __fadd_rn(__fmul_rn(x2, p),  1.48572235717979e-05f);
    p = __fadd_rn(__fmul_rn(x2, p),  6.37261928875436e-04f);
    p = __fadd_rn(__fmul_rn(x2, p),  4.89352455891786e-03f);
    float num = __fmul_rn(x, p);
    float q = 1.19825839466702e-06f;
    q = __fadd_rn(__fmul_rn(x2, q), 1.18534705686654e-04f);
    q = __fadd_rn(__fmul_rn(x2, q), 2.26843463243900e-03f);
    q = __fadd_rn(__fmul_rn(x2, q), 4.89352518554385e-03f);
    float r = __fdiv_rn(num, q);
    return (fabsf(xin) < 0.0004f) ? xin : r;
}

// ---------------- kZ: zero stat accumulators -------------------------------
__global__ void kZ() {
    int i = blockIdx.x * 256 + threadIdx.x;
    if (i < GCH * OUTC) { d_S1[i] = 0; d_S2[i] = 0ull; }
}

// ---------------- kPrep: sign planes (fill + interior in one pass) ---------
__global__ void kPrep(const float* __restrict__ inp) {
    int i = blockIdx.x * 256 + threadIdx.x;         // over 512*1156
    if (i >= BATCH * CIN * 1156) return;
    int bc = i / 1156, p = i - bc * 1156;
    int y = p / 34, x = p - y * 34;
    const int AS = 512 * PSTR;                      // a-plane stride
    int base = bc * PSTR + p;
    if (y == 0 || y == 33 || x == 0 || x == 33) {
        d_SP[base] = 1;
        d_SP[AS + base] = -1;
        d_SP[2 * AS + base] = -1;
        d_SP[3 * AS + base] = -1;
    } else {
        float v = inp[(bc << 10) + (y - 1) * 32 + (x - 1)];
        float r = fminf(fmaxf(v, -1.0f), 1.0f);
        float half = 0.5f;
#pragma unroll
        for (int a = 0; a < ABITS; ++a) {
            bool pos = (r >= 0.0f);
            d_SP[a * AS + base] = pos ? 1 : -1;
            r = __fsub_rn(r, pos ? half : -half);
            half = __fmul_rn(half, 0.5f);
        }
    }
}

// ---------------- kW: weight standardize + 4-bit quantize ------------------
__global__ void kW(const float* __restrict__ wgt) {
    int o = blockIdx.x;                 // 128
    int t = threadIdx.x;                // 64
    __shared__ double red[64], red2[64];
    __shared__ float s_mean, s_std;
    const float* wr = wgt + o * CKTOT;

    double s = 0.0;
    for (int i = t; i < CKTOT; i += 64) s += (double)wr[i];
    red[t] = s; __syncthreads();
    for (int st = 32; st; st >>= 1) { if (t < st) red[t] += red[t + st]; __syncthreads(); }
    if (!t) s_mean = (float)(red[0] / 576.0);
    __syncthreads();
    float mf = s_mean;

    double s1 = 0.0, s2 = 0.0;
    for (int i = t; i < CKTOT; i += 64) {
        float bw = __fsub_rn(wr[i], mf);
        s1 += (double)bw; s2 += (double)bw * (double)bw;
    }
    red[t] = s1; red2[t] = s2; __syncthreads();
    for (int st = 32; st; st >>= 1) {
        if (t < st) { red[t] += red[t + st]; red2[t] += red2[t + st]; }
        __syncthreads();
    }
    if (!t) {
        double mu = red[0] / 576.0;
        double var = (red2[0] - 576.0 * mu * mu) / 575.0;  // ddof=1
        s_std = (float)sqrt(var);
    }
    __syncthreads();
    float stdf = s_std;

    for (int i = t; i < CKTOT; i += 64) {
        float bw = __fsub_rn(wr[i], mf);
        float c = fminf(fmaxf(__fdiv_rn(bw, stdf), -1.0f), 1.0f);
        int m = (int)rintf(__fmul_rn(c, 7.0f));   // round-half-even, like jnp.round
        ((signed char*)d_Wp)[(((unsigned)i >> 2) * OUTC + o) * 4 + (i & 3)] = (signed char)m;
    }
}

// ---------------- kG: fused unfold + exact int8 GEMM (7*lt) ----------------
// grid (2 l-halves, 32 n, 9 g), 256 threads; each thread handles 2 l's.
__global__ void __launch_bounds__(256) kG() {
    __shared__ __align__(16) int ws[OUTC][16];
    __shared__ __align__(16) signed char sgn[9 * PSTR];   // <= 9 channels
    int g = blockIdx.z, n = blockIdx.y, lh = blockIdx.x;
    int tid = threadIdx.x;

    for (int i = tid; i < OUTC * 16; i += 256) {
        int o = i >> 4, q = i & 15;
        ws[o][q] = d_Wp[(16 * g + q) * OUTC + o];
    }
    int c_lo = (64 * g) / 9;
    int cn = min(9, CIN - c_lo);
    {
        const int* src = (const int*)(d_SP + (n * CIN + c_lo) * PSTR);
        int* dst = (int*)sgn;
        int words = cn * (PSTR / 4);
        for (int i = tid; i < words; i += 256) dst[i] = src[i];
    }
    __syncthreads();

    int l0 = lh * 512 + tid;
    int l1 = l0 + 256;
    int px0 = (l0 >> 5) * 34 + (l0 & 31);
    int px1 = (l1 >> 5) * 34 + (l1 & 31);

    int A0[16], A1[16];
#pragma unroll
    for (int q = 0; q < 16; ++q) { A0[q] = 0; A1[q] = 0; }
#pragma unroll
    for (int q = 0; q < 16; ++q) {
#pragma unroll
        for (int s = 0; s < 4; ++s) {
            int ck = 64 * g + q * 4 + s;
            int cq = ck / 9;
            int kp = ck - cq * 9;
            int dy = kp / 3, dx = kp - dy * 3;
            int boff = (cq - c_lo) * PSTR + dy * 34 + dx;   // block-uniform
            unsigned b0 = (unsigned char)sgn[boff + px0];
            unsigned b1 = (unsigned char)sgn[boff + px1];
            A0[q] |= b0 << (8 * s);
            A1[q] |= b1 << (8 * s);
        }
    }

    short* tb = d_t7 + ((g * NTOT + n) << 17) + l0;
    for (int o = 0; o < OUTC; ++o) {
        int a0 = 0, a1 = 0;
#pragma unroll
        for (int q4 = 0; q4 < 4; ++q4) {
            int4 wv = *(const int4*)&ws[o][q4 * 4];
            a0 = __dp4a(A0[q4 * 4 + 0], wv.x, a0); a1 = __dp4a(A1[q4 * 4 + 0], wv.x, a1);
            a0 = __dp4a(A0[q4 * 4 + 1], wv.y, a0); a1 = __dp4a(A1[q4 * 4 + 1], wv.y, a1);
            a0 = __dp4a(A0[q4 * 4 + 2], wv.z, a0); a1 = __dp4a(A1[q4 * 4 + 2], wv.z, a1);
            a0 = __dp4a(A0[q4 * 4 + 3], wv.w, a0); a1 = __dp4a(A1[q4 * 4 + 3], wv.w, a1);
        }
        tb[o << 10] = (short)a0;
        tb[(o << 10) + 256] = (short)a1;
    }
}

// ---------------- kStats: exact BN sums per (g,o), high-MLP + atomics ------
// grid (1152, 8), block 128: each block reads 4 n-slabs of one (g,o) row
// with int4 loads (4 independent 16B loads in flight per thread).
__global__ void __launch_bounds__(128) kStats() {
    int go = blockIdx.x;            // 0..1151
    int g = go >> 7, o = go & 127;
    int ng = blockIdx.y;            // 0..7 -> n = ng*4 + i
    int t = threadIdx.x;            // 128 (one int4 per n-slab)
    const short* base = d_t7 + ((g * NTOT + ng * 4) << 17) + (o << 10);

    int4 v0 = ((const int4*)(base          ))[t];
    int4 v1 = ((const int4*)(base + (1<<17)))[t];
    int4 v2 = ((const int4*)(base + (2<<17)))[t];
    int4 v3 = ((const int4*)(base + (3<<17)))[t];

    int s1 = 0, s2 = 0;   // per-thread: 32 values, |m|<=448 -> s2 <= 6.4e6
#define ACC(w) { int mA = (short)((w) & 0xFFFF); int mB = ((w) >> 16); \
                 s1 += mA + mB; s2 += mA * mA + mB * mB; }
    ACC(v0.x) ACC(v0.y) ACC(v0.z) ACC(v0.w)
    ACC(v1.x) ACC(v1.y) ACC(v1.z) ACC(v1.w)
    ACC(v2.x) ACC(v2.y) ACC(v2.z) ACC(v2.w)
    ACC(v3.x) ACC(v3.y) ACC(v3.z) ACC(v3.w)
#undef ACC

    // warp reduce (block sum of s2 <= 8.2e8, fits int)
#pragma unroll
    for (int d = 16; d; d >>= 1) {
        s1 += __shfl_xor_sync(0xFFFFFFFFu, s1, d);
        s2 += __shfl_xor_sync(0xFFFFFFFFu, s2, d);
    }
    __shared__ int r1[4], r2[4];
    int w = t >> 5;
    if ((t & 31) == 0) { r1[w] = s1; r2[w] = s2; }
    __syncthreads();
    if (t == 0) {
        int t1 = r1[0] + r1[1] + r1[2] + r1[3];
        int t2 = r2[0] + r2[1] + r2[2] + r2[3];
        atomicAdd(&d_S1[go], t1);
        atomicAdd(&d_S2[go], (unsigned long long)(long long)t2);
    }
}

// ---------------- kT: finalize BN stats + tabulate tanh per (g,o) ----------
// Bit-identical op sequence to the previously-passing per-element path.
__global__ void kT(const float* __restrict__ gamma, const float* __restrict__ beta) {
    int go = blockIdx.x;               // 0..1151
    int o = go & 127;
    __shared__ float s_mn, s_sf;
    if (threadIdx.x == 0) {
        double mu  = (double)d_S1[go] / (7.0 * 32768.0);
        double ex2 = (double)(long long)d_S2[go] / (49.0 * 32768.0);
        double var = ex2 - mu * mu;          // biased (BN train)
        s_mn = (float)mu;
        s_sf = __fsqrt_rn(__fadd_rn((float)var, 1e-5f));
    }
    __syncthreads();
    float mn = s_mn, sd = s_sf;
    float gam = gamma[o], bet = beta[o];
    for (int idx = threadIdx.x; idx < 897; idx += 256) {
        float lt = __fdiv_rn(__int2float_rn(idx - 448), 7.0f);
        float normed = __fadd_rn(__fmul_rn(__fdiv_rn(__fsub_rn(lt, mn), sd), gam), bet);
        float t = tanh_xla(__fmul_rn(normed, 4.0f));
        d_T[go * TROW + idx] = t;
    }
}

// ---------------- kE: threefry + table lookup + binarize + recombine -------
// one block per (o, b): 1024 threads = all l; table staged once per block.
__global__ void __launch_bounds__(1024) kE(float* __restrict__ out, Keys keys) {
    __shared__ float tt[GCH][TROW];
    int l = threadIdx.x;                       // 0..1023
    int o = blockIdx.x;                        // 0..127
    int b = blockIdx.y;                        // 0..7
#pragma unroll
    for (int g = 0; g < GCH; ++g)
        if (l < 897) tt[g][l] = d_T[(g * OUTC + o) * TROW + l];
    __syncthreads();

    int S[ABITS] = {0, 0, 0, 0};
#pragma unroll 1
    for (int g = 0; g < GCH; ++g) {
        unsigned k0 = keys.v[2 * g], k1 = keys.v[2 * g + 1];
#pragma unroll
        for (int a = 0; a < ABITS; ++a) {
            int n = a * 8 + b;
            int m7 = d_t7[((g * NTOT + n) << 17) + (o << 10) + l];
            float t = tt[g][m7 + 448];
            unsigned j = ((unsigned)(n * OUTC + o) << 10) + (unsigned)l;
            unsigned r0, r1; tf2x32(k0, k1, 0u, j, r0, r1);
            unsigned bits = r0 ^ r1;
            float u = __fsub_rn(__uint_as_float((bits >> 9) | 0x3f800000u), 1.0f);
            float rnd = __fadd_rn(__fmul_rn(u, 2.0f), -1.0f);
            int s = (t > rnd) ? 1 : -1;
            s = (t == 0.0f) ? 0 : s;      // normed==0 <=> t==+-0 (tanh_xla small-x path)
            S[a] += s;
        }
    }
    const float wts[ABITS] = {0.5f, 0.25f, 0.125f, 0.0625f};
    float acc = 0.0f;
#pragma unroll
    for (int a = 0; a < ABITS; ++a)
        acc = __fadd_rn(acc, __fmul_rn(__fdiv_rn((float)S[a], 9.0f), wts[a]));
    out[((b * OUTC + o) << 10) + l] = acc;
}

// ---------------------------------------------------------------------------
extern "C" void kernel_launch(void* const* d_in, const int* in_sizes, int n_in,
                              void* d_out, int out_size) {
    const float* inp   = (const float*)d_in[0];   // [8,64,32,32]
    const float* wgt   = (const float*)d_in[1];   // [128,64,3,3]
    const float* gamma = (const float*)d_in[2];   // [128]
    const float* beta  = (const float*)d_in[3];   // [128]
    float* out = (float*)d_out;                   // [8,128,32,32]

    // host-side key derivation: keys = split(key(42), 9) in partitionable mode
    Keys ks;
    for (int g = 0; g < GCH; ++g) {
        unsigned o0, o1;
        tf2x32(0u, 42u, 0u, (unsigned)g, o0, o1);
        ks.v[2 * g] = o0; ks.v[2 * g + 1] = o1;
    }

    kZ<<<(GCH * OUTC + 255) / 256, 256>>>();
    kPrep<<<(BATCH * CIN * 1156 + 255) / 256, 256>>>(inp);
    kW<<<OUTC, 64>>>(wgt);
    kG<<<dim3(2, NTOT, GCH), 256>>>();
    kStats<<<dim3(GCH * OUTC, 8), 128>>>();
    kT<<<GCH * OUTC, 256>>>(gamma, beta);
    kE<<<dim3(OUTC, BATCH), 1024>>>(out, ks);
}